// round 16
// baseline (speedup 1.0000x reference)
#include <cuda_runtime.h>
#include <cuda_fp16.h>
#include <math.h>

#define BB 8
#define CIN 512
#define NPIX 4096
#define CKD 64
#define COUT 128
#define KCONV 4608

typedef __half h16;

// ---------------- device scratch ----------------
__device__ __align__(16) h16 g_XT[(size_t)BB*NPIX*512];        // [b][n][c512] fp16
__device__ __align__(16) h16 g_fuseT[(size_t)BB*66*66*512];    // [b][y][x][c512] fp16
__device__ __align__(16) h16 g_Wqk[128*512];                   // hi only (64 q + 64 k rows)
__device__ __align__(16) h16 g_Wv[512*512];                    // hi only
__device__ __align__(16) h16 g_Wc[128*KCONV];                  // hi only, k'=(r9*512+ic)
__device__ __align__(16) h16 g_Vh[(size_t)BB*CIN*2*NPIX];      // [b][c][hi|lo][n]
__device__ __align__(16) h16 g_Kh[(size_t)BB*CKD*2*NPIX];      // [b][k][hi|lo][n]
__device__ __align__(16) h16 g_QT[(size_t)BB*NPIX*64];         // [b][n][hi64]
__device__ __align__(16) h16 g_WosH[BB*CIN*128];               // [b][o][hi64|lo64]
__device__ float g_simP[BB*4*CIN*CKD];
__device__ float g_simT[BB*CIN*CKD];

// ---------------- helpers ----------------
__device__ __forceinline__ unsigned pk2h(float a, float b) {
    __half2 h = __floats2half2_rn(a, b);
    return *reinterpret_cast<unsigned*>(&h);
}
__device__ __forceinline__ float hhi_f(float x) { return __half2float(__float2half_rn(x)); }
__device__ __forceinline__ void pack8h(const float* f, unsigned* hi) {
    #pragma unroll
    for (int i = 0; i < 4; i++) hi[i] = pk2h(f[2*i], f[2*i+1]);
}
__device__ __forceinline__ unsigned su32(const void* p) {
    return (unsigned)__cvta_generic_to_shared(p);
}
__device__ __forceinline__ void cpa16(void* sdst, const void* gsrc) {
    asm volatile("cp.async.cg.shared.global [%0], [%1], 16;" :: "r"(su32(sdst)), "l"(gsrc));
}
__device__ __forceinline__ void cp_commit() { asm volatile("cp.async.commit_group;" ::: "memory"); }
__device__ __forceinline__ void cp_wait2()  { asm volatile("cp.async.wait_group 2;" ::: "memory"); }
__device__ __forceinline__ void cp_wait1()  { asm volatile("cp.async.wait_group 1;" ::: "memory"); }
__device__ __forceinline__ void cp_wait0()  { asm volatile("cp.async.wait_group 0;" ::: "memory"); }
__device__ __forceinline__ void mma16816h(float* d, const unsigned* a, const unsigned* b) {
    asm("mma.sync.aligned.m16n8k16.row.col.f32.f16.f16.f32 "
        "{%0,%1,%2,%3},{%4,%5,%6,%7},{%8,%9},{%0,%1,%2,%3};"
        : "+f"(d[0]), "+f"(d[1]), "+f"(d[2]), "+f"(d[3])
        : "r"(a[0]), "r"(a[1]), "r"(a[2]), "r"(a[3]), "r"(b[0]), "r"(b[1]));
}
__device__ __forceinline__ void ldm4(unsigned* r, const h16* p) {
    asm volatile("ldmatrix.sync.aligned.m8n8.x4.shared.b16 {%0,%1,%2,%3}, [%4];"
        : "=r"(r[0]), "=r"(r[1]), "=r"(r[2]), "=r"(r[3]) : "r"(su32(p)));
}

// ---------------- prepxt: xt transpose + weight splits + conv permute + border zero ----
__global__ __launch_bounds__(256) void prepxt(
    const float* __restrict__ x,
    const float* __restrict__ wq, const float* __restrict__ wk,
    const float* __restrict__ wv, const float* __restrict__ ws)
{
    __shared__ float tile[32][65];
    const int bid = blockIdx.x;
    const int t = threadIdx.x;
    if (bid < 8192) {
        // xt: decode (n0 64-blocks, c0 16-blocks, b 8)
        int b  = bid >> 10;            // bid / 1024
        int r2 = bid & 1023;
        int c0 = (r2 >> 6) * 32;       // 16 c-blocks
        int n0 = (r2 & 63) * 64;       // 64 n-blocks
        {
            int r = t >> 3, nq = (t & 7) * 8;
            const float* src = x + ((size_t)b * CIN + c0 + r) * NPIX + n0 + nq;
            float4 a = *reinterpret_cast<const float4*>(src);
            float4 c = *reinterpret_cast<const float4*>(src + 4);
            tile[r][nq+0]=a.x; tile[r][nq+1]=a.y; tile[r][nq+2]=a.z; tile[r][nq+3]=a.w;
            tile[r][nq+4]=c.x; tile[r][nq+5]=c.y; tile[r][nq+6]=c.z; tile[r][nq+7]=c.w;
        }
        __syncthreads();
        {
            int xc = t & 63, grp = t >> 6;
            float f[8];
            #pragma unroll
            for (int i = 0; i < 8; i++) f[i] = tile[grp*8 + i][xc];
            unsigned hh[4];
            pack8h(f, hh);
            h16* d = g_XT + ((size_t)b * NPIX + n0 + xc) * 512 + c0 + grp*8;
            *reinterpret_cast<uint4*>(d) = make_uint4(hh[0], hh[1], hh[2], hh[3]);
        }
        return;
    }
    const int pb = bid - 8192;
    if (pb < 160) {
        const float* src;
        h16* dst;
        int idx;
        if (pb < 16)      { src = wq; dst = g_Wqk;            idx = pb*256 + t; }
        else if (pb < 32) { src = wk; dst = g_Wqk + 64*512;   idx = (pb-16)*256 + t; }
        else              { src = wv; dst = g_Wv;             idx = (pb-32)*256 + t; }
        int m = idx >> 6, kg = idx & 63;
        float f[8];
        *reinterpret_cast<float4*>(f)     = *reinterpret_cast<const float4*>(src + (size_t)m*512 + kg*8);
        *reinterpret_cast<float4*>(f + 4) = *reinterpret_cast<const float4*>(src + (size_t)m*512 + kg*8 + 4);
        unsigned hi[4];
        pack8h(f, hi);
        *reinterpret_cast<uint4*>(dst + (size_t)m * 512 + kg*8) = make_uint4(hi[0], hi[1], hi[2], hi[3]);
    } else if (pb < 448) {
        int idx = (pb - 160) * 256 + t;
        if (idx >= 128 * 576) return;
        int oc = idx / 576, kg = idx - oc * 576;
        int kp0 = kg * 8;
        int r9 = kp0 >> 9, ic = kp0 & 511;
        float f[8];
        #pragma unroll
        for (int j = 0; j < 8; j++)
            f[j] = ws[(size_t)oc * KCONV + (ic + j) * 9 + r9];
        unsigned hi[4];
        pack8h(f, hi);
        *reinterpret_cast<uint4*>(g_Wc + (size_t)oc * KCONV + kp0) = make_uint4(hi[0], hi[1], hi[2], hi[3]);
    } else {
        int idx = (pb - 448) * 256 + t;
        if (idx >= BB * 260 * 64) return;
        int c16 = idx & 63;
        int r = idx >> 6;
        int b = r / 260, p = r - b * 260;
        int y, x2;
        if (p < 66)       { y = 0;  x2 = p; }
        else if (p < 132) { y = 65; x2 = p - 66; }
        else if (p < 196) { y = p - 132 + 1; x2 = 0; }
        else              { y = p - 196 + 1; x2 = 65; }
        uint4* d = reinterpret_cast<uint4*>(g_fuseT + (((size_t)b*66 + y)*66 + x2)*512);
        d[c16] = make_uint4(0, 0, 0, 0);
    }
}

// ---------------- qkv_mma: merged qk (y==4) + V (y<4). 128 thr, 64x64 warp tiles ----
__global__ __launch_bounds__(128) void qkv_mma(
    const float* __restrict__ sq, const float* __restrict__ bq,
    const float* __restrict__ sk, const float* __restrict__ bk,
    const float* __restrict__ sv, const float* __restrict__ bv)
{
    constexpr int NSTEP = 512 / 16;
    __shared__ __align__(16) h16 sm[3][2][128][24];   // 36KB, 3 stages
    const int bidx = blockIdx.z;
    const int n0 = blockIdx.x * 128;
    const bool isQK = (blockIdx.y == 4);
    const int row0 = isQK ? 0 : blockIdx.y * 128;
    const int t = threadIdx.x;
    const int lane = t & 31, w = t >> 5, wm = w >> 1, wn = w & 1;

    float acc[4][8][4];
    #pragma unroll
    for (int i = 0; i < 4; i++)
        #pragma unroll
        for (int j = 0; j < 8; j++)
            #pragma unroll
            for (int c = 0; c < 4; c++) acc[i][j][c] = 0.f;

    const h16* aSrc = (isQK ? g_Wqk : g_Wv + (size_t)row0 * 512) + (size_t)t * 512;
    const h16* bSrc = g_XT + ((size_t)bidx * NPIX + n0 + t) * 512;

    auto load = [&](int st, int kc) {
        cpa16(&sm[st][0][t][0], aSrc + kc);
        cpa16(&sm[st][0][t][8], aSrc + kc + 8);
        cpa16(&sm[st][1][t][0], bSrc + kc);
        cpa16(&sm[st][1][t][8], bSrc + kc + 8);
        cp_commit();
    };

    const int ar  = wm*64 + (lane & 15);
    const int acl = (lane >> 4) * 8;
    const int br  = wn*64 + ((lane >> 4) << 3) + (lane & 7);
    const int bcl = ((lane >> 3) & 1) * 8;

    load(0, 0);
    load(1, 16);
    int stq = 2;
    #pragma unroll 1
    for (int kt = 0; kt < NSTEP; kt++) {
        int cur = kt % 3;
        if (kt + 2 < NSTEP) {
            load(stq, (kt+2)*16);
            stq = (stq + 1) % 3;
            cp_wait2();
        } else if (kt + 1 < NSTEP) {
            cp_wait1();
        } else {
            cp_wait0();
        }
        __syncthreads();

        unsigned ah[4][4], bfr[8][2];
        #pragma unroll
        for (int mt = 0; mt < 4; mt++) ldm4(ah[mt], &sm[cur][0][ar + mt*16][acl]);
        #pragma unroll
        for (int g = 0; g < 4; g++) ldm4(&bfr[2*g][0], &sm[cur][1][br + g*16][bcl]);
        #pragma unroll
        for (int mt = 0; mt < 4; mt++)
            #pragma unroll
            for (int nt = 0; nt < 8; nt++)
                mma16816h(acc[mt][nt], ah[mt], bfr[nt]);
        __syncthreads();
    }

    const int qr = lane >> 2, qc = (lane & 3) * 2;

    if (isQK) {
        // affine per row (wm0 rows = Q 0..63, wm1 rows = K 0..63)
        #pragma unroll
        for (int mt = 0; mt < 4; mt++)
            #pragma unroll
            for (int h = 0; h < 2; h++) {
                int ri = (mt*16 + qr + 8*h) & 63;
                float sc = wm ? sk[ri] : sq[ri];
                float bi = wm ? bk[ri] : bq[ri];
                #pragma unroll
                for (int nt = 0; nt < 8; nt++) {
                    acc[mt][nt][2*h]   = fmaf(acc[mt][nt][2*h],   sc, bi);
                    acc[mt][nt][2*h+1] = fmaf(acc[mt][nt][2*h+1], sc, bi);
                }
            }
        float inv[8][2];
        #pragma unroll
        for (int nt = 0; nt < 8; nt++)
            #pragma unroll
            for (int j = 0; j < 2; j++) {
                float ss = 0.f;
                #pragma unroll
                for (int mt = 0; mt < 4; mt++)
                    ss += acc[mt][nt][j]*acc[mt][nt][j] + acc[mt][nt][2+j]*acc[mt][nt][2+j];
                ss += __shfl_xor_sync(0xffffffffu, ss, 4);
                ss += __shfl_xor_sync(0xffffffffu, ss, 8);
                ss += __shfl_xor_sync(0xffffffffu, ss, 16);
                inv[nt][j] = 1.f / fmaxf(sqrtf(ss), 1e-12f);
            }
        if (wm == 0) {
            h16* qd = g_QT + (size_t)bidx * NPIX * 64;
            #pragma unroll
            for (int mt = 0; mt < 4; mt++)
                #pragma unroll
                for (int h = 0; h < 2; h++) {
                    int ch = (mt*16 + qr + 8*h) & 63;
                    #pragma unroll
                    for (int nt = 0; nt < 8; nt++) {
                        int col = n0 + wn*64 + nt*8 + qc;
                        qd[(size_t)col*64 + ch]     = __float2half_rn(acc[mt][nt][2*h]   * inv[nt][0]);
                        qd[(size_t)(col+1)*64 + ch] = __float2half_rn(acc[mt][nt][2*h+1] * inv[nt][1]);
                    }
                }
        } else {
            #pragma unroll
            for (int mt = 0; mt < 4; mt++)
                #pragma unroll
                for (int h = 0; h < 2; h++) {
                    int ch = (mt*16 + qr + 8*h) & 63;
                    h16* kd = g_Kh + ((size_t)bidx * CKD + ch) * 2 * NPIX;
                    #pragma unroll
                    for (int nt = 0; nt < 8; nt++) {
                        int col = n0 + wn*64 + nt*8 + qc;
                        float v0 = acc[mt][nt][2*h]   * inv[nt][0];
                        float v1 = acc[mt][nt][2*h+1] * inv[nt][1];
                        *reinterpret_cast<unsigned*>(&kd[col]) = pk2h(v0, v1);
                        *reinterpret_cast<unsigned*>(&kd[NPIX + col]) =
                            pk2h(v0 - hhi_f(v0), v1 - hhi_f(v1));
                    }
                }
        }
    } else {
        #pragma unroll
        for (int mt = 0; mt < 4; mt++)
            #pragma unroll
            for (int h = 0; h < 2; h++) {
                int row = row0 + wm*64 + mt*16 + qr + 8*h;
                float sc = sv[row], bi = bv[row];
                h16* vd = g_Vh + ((size_t)bidx * CIN + row) * 2 * NPIX;
                #pragma unroll
                for (int nt = 0; nt < 8; nt++) {
                    int col = n0 + wn*64 + nt*8 + qc;
                    float v0 = fmaxf(fmaf(acc[mt][nt][2*h],   sc, bi), 0.f);
                    float v1 = fmaxf(fmaf(acc[mt][nt][2*h+1], sc, bi), 0.f);
                    *reinterpret_cast<unsigned*>(&vd[col]) = pk2h(v0, v1);
                    *reinterpret_cast<unsigned*>(&vd[NPIX + col]) =
                        pk2h(v0 - hhi_f(v0), v1 - hhi_f(v1));
                }
            }
    }
}

// ---------------- conv GEMM: 256 threads, 64x32 warp tiles, 3-stage ----------------
__global__ __launch_bounds__(256) void conv_mma(
    const float* __restrict__ s0, const float* __restrict__ b0v,
    float* __restrict__ outp)
{
    constexpr int KD = KCONV;
    constexpr int NSTEP = KD / 16;
    __shared__ __align__(16) h16 sm[3][2][128][24];   // 36KB, 3 stages
    const int bidx = blockIdx.z;
    const int n0 = blockIdx.x * 128;
    const int t = threadIdx.x;
    const int lane = t & 31, w = t >> 5, wm = w >> 2, wn = w & 3;

    float acc[4][4][4];
    #pragma unroll
    for (int i = 0; i < 4; i++)
        #pragma unroll
        for (int j = 0; j < 4; j++)
            #pragma unroll
            for (int c = 0; c < 4; c++) acc[i][j][c] = 0.f;

    const int lt = t >> 7, lr = t & 127;
    const h16* aSrc = g_Wc + (size_t)lr * KD;
    int yi, xi;
    { int p = n0 + lr; yi = p >> 6; xi = p & 63; }

    auto load = [&](int st, int kc) {
        if (lt == 0) {
            cpa16(&sm[st][0][lr][0], aSrc + kc);
            cpa16(&sm[st][0][lr][8], aSrc + kc + 8);
        } else {
            int r9 = kc >> 9, kin = kc & 511;
            int dy = r9 / 3, dx = r9 - dy*3;
            const h16* bp = g_fuseT + (((size_t)bidx*66 + yi + dy)*66 + xi + dx)*512 + kin;
            cpa16(&sm[st][1][lr][0], bp);
            cpa16(&sm[st][1][lr][8], bp + 8);
        }
        cp_commit();
    };

    const int ar  = wm*64 + (lane & 15);
    const int acl = (lane >> 4) * 8;
    const int br  = wn*32 + ((lane >> 4) << 3) + (lane & 7);
    const int bcl = ((lane >> 3) & 1) * 8;

    load(0, 0);
    load(1, 16);
    int stq = 2;
    #pragma unroll 1
    for (int kt = 0; kt < NSTEP; kt++) {
        int cur = kt % 3;
        if (kt + 2 < NSTEP) {
            load(stq, (kt+2)*16);
            stq = (stq + 1) % 3;
            cp_wait2();
        } else if (kt + 1 < NSTEP) {
            cp_wait1();
        } else {
            cp_wait0();
        }
        __syncthreads();

        unsigned ah[4][4], bfr[4][2];
        #pragma unroll
        for (int mt = 0; mt < 4; mt++) ldm4(ah[mt], &sm[cur][0][ar + mt*16][acl]);
        #pragma unroll
        for (int g = 0; g < 2; g++) ldm4(&bfr[2*g][0], &sm[cur][1][br + g*16][bcl]);
        #pragma unroll
        for (int mt = 0; mt < 4; mt++)
            #pragma unroll
            for (int nt = 0; nt < 4; nt++)
                mma16816h(acc[mt][nt], ah[mt], bfr[nt]);
        __syncthreads();
    }

    const int qr = lane >> 2, qc = (lane & 3) * 2;
    #pragma unroll
    for (int mt = 0; mt < 4; mt++)
        #pragma unroll
        for (int h = 0; h < 2; h++) {
            int row = wm*64 + mt*16 + qr + 8*h;
            float sc = s0[row], bi = b0v[row];
            #pragma unroll
            for (int nt = 0; nt < 4; nt++) {
                int col = n0 + wn*32 + nt*8 + qc;
                float2 o;
                o.x = fmaxf(fmaf(acc[mt][nt][2*h],   sc, bi), 0.f);
                o.y = fmaxf(fmaf(acc[mt][nt][2*h+1], sc, bi), 0.f);
                *reinterpret_cast<float2*>(
                    &outp[((size_t)bidx * COUT + row) * NPIX + col]) = o;
            }
        }
}

// ---------------- sim via mma: 3-pass on split V/K ----------------
__global__ __launch_bounds__(128) void sim_mma()
{
    __shared__ __align__(16) h16 sm[2][4][128][24];   // 48KB
    const int b = blockIdx.z, chunk = blockIdx.y, c0 = blockIdx.x * 128;
    const int t = threadIdx.x;
    const int lane = t & 31, w = t >> 5, wm = w >> 1, wn = w & 1;

    float acc[4][4][4];
    #pragma unroll
    for (int i = 0; i < 4; i++)
        #pragma unroll
        for (int j = 0; j < 4; j++)
            #pragma unroll
            for (int c = 0; c < 4; c++) acc[i][j][c] = 0.f;

    const h16* aSrc = g_Vh + ((size_t)b * CIN + c0 + t) * 2 * NPIX + chunk * 1024;
    const h16* bSrc = g_Kh + ((size_t)b * CKD + (t & 63)) * 2 * NPIX + chunk * 1024;

    auto load = [&](int st, int kc) {
        cpa16(&sm[st][0][t][0], aSrc + kc);
        cpa16(&sm[st][0][t][8], aSrc + kc + 8);
        cpa16(&sm[st][1][t][0], aSrc + NPIX + kc);
        cpa16(&sm[st][1][t][8], aSrc + NPIX + kc + 8);
        if (t < 64) {
            cpa16(&sm[st][2][t][0], bSrc + kc);
            cpa16(&sm[st][2][t][8], bSrc + kc + 8);
            cpa16(&sm[st][3][t][0], bSrc + NPIX + kc);
            cpa16(&sm[st][3][t][8], bSrc + NPIX + kc + 8);
        }
        cp_commit();
    };

    const int ar  = wm*64 + (lane & 15);
    const int acl = (lane >> 4) * 8;
    const int br  = wn*32 + ((lane >> 4) << 3) + (lane & 7);
    const int bcl = ((lane >> 3) & 1) * 8;

    load(0, 0);
    #pragma unroll 1
    for (int kt = 0; kt < 64; kt++) {
        int cur = kt & 1;
        if (kt + 1 < 64) { load(cur ^ 1, (kt+1)*16); cp_wait1(); }
        else              cp_wait0();
        __syncthreads();

        unsigned ah[4][4], al[4][4], bh[4][2], bl[4][2];
        #pragma unroll
        for (int mt = 0; mt < 4; mt++) ldm4(ah[mt], &sm[cur][0][ar + mt*16][acl]);
        #pragma unroll
        for (int mt = 0; mt < 4; mt++) ldm4(al[mt], &sm[cur][1][ar + mt*16][acl]);
        #pragma unroll
        for (int g = 0; g < 2; g++) ldm4(&bh[2*g][0], &sm[cur][2][br + g*16][bcl]);
        #pragma unroll
        for (int g = 0; g < 2; g++) ldm4(&bl[2*g][0], &sm[cur][3][br + g*16][bcl]);
        #pragma unroll
        for (int mt = 0; mt < 4; mt++)
            #pragma unroll
            for (int nt = 0; nt < 4; nt++)
                mma16816h(acc[mt][nt], ah[mt], bh[nt]);
        #pragma unroll
        for (int mt = 0; mt < 4; mt++)
            #pragma unroll
            for (int nt = 0; nt < 4; nt++)
                mma16816h(acc[mt][nt], al[mt], bh[nt]);
        #pragma unroll
        for (int mt = 0; mt < 4; mt++)
            #pragma unroll
            for (int nt = 0; nt < 4; nt++)
                mma16816h(acc[mt][nt], ah[mt], bl[nt]);
        __syncthreads();
    }

    const int qr = lane >> 2, qc = (lane & 3) * 2;
    float* pb = g_simP + (size_t)(b*4 + chunk) * CIN * CKD;
    #pragma unroll
    for (int mt = 0; mt < 4; mt++)
        #pragma unroll
        for (int h = 0; h < 2; h++) {
            int row = c0 + wm*64 + mt*16 + qr + 8*h;
            #pragma unroll
            for (int nt = 0; nt < 4; nt++) {
                int col = wn*32 + nt*8 + qc;
                float2 o = make_float2(acc[mt][nt][2*h], acc[mt][nt][2*h+1]);
                *reinterpret_cast<float2*>(&pb[(size_t)row * CKD + col]) = o;
            }
        }
}

__global__ __launch_bounds__(256) void sim_reduce()
{
    int idx = blockIdx.x * 256 + threadIdx.x;
    if (idx >= BB * CIN * CKD) return;
    int b = idx / (CIN * CKD);
    int rem = idx - b * CIN * CKD;
    float s = 0.f;
    #pragma unroll
    for (int p = 0; p < 4; p++)
        s += g_simP[(size_t)(b*4 + p) * CIN * CKD + rem];
    g_simT[idx] = s;
}

// ---------------- wos: Wo @ simT -> split fp16 [b][o][hi64|lo64] ----------------
__global__ __launch_bounds__(256) void wos_kernel(const float* __restrict__ wo)
{
    __shared__ __align__(16) float As[16][64];
    __shared__ __align__(16) float Bs[16][64];
    const int b = blockIdx.y;
    const int row0 = blockIdx.x * 64;
    const float* ST = g_simT + (size_t)b * CIN * CKD;
    const int t = threadIdx.x;
    const int tr = t >> 4, tc = t & 15;
    float acc[4][4];
    #pragma unroll
    for (int i = 0; i < 4; i++)
        #pragma unroll
        for (int j = 0; j < 4; j++) acc[i][j] = 0.f;

    for (int kb = 0; kb < CIN; kb += 16) {
        {
            int r  = t >> 2;
            int k4 = (t & 3) << 2;
            float4 va = *reinterpret_cast<const float4*>(wo + (size_t)(row0 + r) * CIN + kb + k4);
            As[k4+0][r] = va.x; As[k4+1][r] = va.y; As[k4+2][r] = va.z; As[k4+3][r] = va.w;
            int kk = t >> 4;
            int n4 = (t & 15) << 2;
            *reinterpret_cast<float4*>(&Bs[kk][n4]) =
                *reinterpret_cast<const float4*>(ST + (size_t)(kb + kk) * CKD + n4);
        }
        __syncthreads();
        #pragma unroll
        for (int kk = 0; kk < 16; kk++) {
            float4 a = *reinterpret_cast<float4*>(&As[kk][tr*4]);
            float4 bbv = *reinterpret_cast<float4*>(&Bs[kk][tc*4]);
            float av[4] = {a.x,a.y,a.z,a.w};
            float bv[4] = {bbv.x,bbv.y,bbv.z,bbv.w};
            #pragma unroll
            for (int i = 0; i < 4; i++)
                #pragma unroll
                for (int j = 0; j < 4; j++)
                    acc[i][j] = fmaf(av[i], bv[j], acc[i][j]);
        }
        __syncthreads();
    }
    #pragma unroll
    for (int i = 0; i < 4; i++) {
        int o = row0 + tr * 4 + i;
        float v0 = acc[i][0], v1 = acc[i][1], v2 = acc[i][2], v3 = acc[i][3];
        h16* d = g_WosH + ((size_t)b * CIN + o) * 128 + tc*4;
        *reinterpret_cast<uint2*>(d) =
            make_uint2(pk2h(v0, v1), pk2h(v2, v3));
        *reinterpret_cast<uint2*>(d + 64) =
            make_uint2(pk2h(v0 - hhi_f(v0), v1 - hhi_f(v1)),
                       pk2h(v2 - hhi_f(v2), v3 - hhi_f(v3)));
    }
}

// ---------------- fuse via mma: 2-pass (Wos hi+lo, Q hi) ----------------
__global__ __launch_bounds__(128) void fuse_mma(
    const float* __restrict__ x, const float* __restrict__ up,
    const float* __restrict__ so, const float* __restrict__ bo)
{
    __shared__ __align__(16) h16 sm[2][3][128][24];   // 36KB; reused as transpose buf
    const int b = blockIdx.z;
    const int n0 = blockIdx.x * 128;
    const int row0 = blockIdx.y * 128;
    const int t = threadIdx.x;
    const int lane = t & 31, w = t >> 5, wm = w >> 1, wn = w & 1;

    float acc[4][8][4];
    #pragma unroll
    for (int i = 0; i < 4; i++)
        #pragma unroll
        for (int j = 0; j < 8; j++)
            #pragma unroll
            for (int c = 0; c < 4; c++) acc[i][j][c] = 0.f;

    const h16* aSrc = g_WosH + ((size_t)b * CIN + row0 + t) * 128;
    const h16* bSrc = g_QT   + ((size_t)b * NPIX + n0 + t) * 64;

    auto load = [&](int st, int kc) {
        cpa16(&sm[st][0][t][0], aSrc + kc);
        cpa16(&sm[st][0][t][8], aSrc + kc + 8);
        cpa16(&sm[st][1][t][0], aSrc + 64 + kc);
        cpa16(&sm[st][1][t][8], aSrc + 64 + kc + 8);
        cpa16(&sm[st][2][t][0], bSrc + kc);
        cpa16(&sm[st][2][t][8], bSrc + kc + 8);
        cp_commit();
    };

    const int ar  = wm*64 + (lane & 15);
    const int acl = (lane >> 4) * 8;
    const int br  = wn*64 + ((lane >> 4) << 3) + (lane & 7);
    const int bcl = ((lane >> 3) & 1) * 8;

    load(0, 0);
    #pragma unroll 1
    for (int kt = 0; kt < 4; kt++) {
        int cur = kt & 1;
        if (kt + 1 < 4) { load(cur ^ 1, (kt+1)*16); cp_wait1(); }
        else             cp_wait0();
        __syncthreads();

        unsigned ah[4][4], al[4][4], bh[8][2];
        #pragma unroll
        for (int mt = 0; mt < 4; mt++) ldm4(ah[mt], &sm[cur][0][ar + mt*16][acl]);
        #pragma unroll
        for (int mt = 0; mt < 4; mt++) ldm4(al[mt], &sm[cur][1][ar + mt*16][acl]);
        #pragma unroll
        for (int g = 0; g < 4; g++) ldm4(&bh[2*g][0], &sm[cur][2][br + g*16][bcl]);
        #pragma unroll
        for (int mt = 0; mt < 4; mt++)
            #pragma unroll
            for (int nt = 0; nt < 8; nt++)
                mma16816h(acc[mt][nt], ah[mt], bh[nt]);        // hi*hi
        #pragma unroll
        for (int mt = 0; mt < 4; mt++)
            #pragma unroll
            for (int nt = 0; nt < 8; nt++)
                mma16816h(acc[mt][nt], al[mt], bh[nt]);        // lo*hi
        __syncthreads();
    }

    const int qr = lane >> 2, qc = (lane & 3) * 2;
    h16 (*trans)[136] = reinterpret_cast<h16 (*)[136]>(&sm[0][0][0][0]);
    #pragma unroll
    for (int mt = 0; mt < 4; mt++)
        #pragma unroll
        for (int h = 0; h < 2; h++) {
            int crl = wm*64 + mt*16 + qr + 8*h;
            int row = row0 + crl;
            float sc = so[row], bi = bo[row];
            #pragma unroll
            for (int nt = 0; nt < 8; nt++) {
                int cl = wn*64 + nt*8 + qc;
                size_t xoff = ((size_t)b * CIN + row) * NPIX + n0 + cl;
                float2 xv = *reinterpret_cast<const float2*>(x + xoff);
                float2 uv = *reinterpret_cast<const float2*>(up + xoff);
                float v0 = fmaxf(fmaf(acc[mt][nt][2*h],   sc, bi), 0.f) + xv.x + uv.x;
                float v1 = fmaxf(fmaf(acc[mt][nt][2*h+1], sc, bi), 0.f) + xv.y + uv.y;
                trans[cl][crl]     = __float2half_rn(v0);
                trans[cl + 1][crl] = __float2half_rn(v1);
            }
        }
    __syncthreads();
    {
        int p = n0 + t;
        int y = p >> 6, xx = p & 63;
        h16* dst = g_fuseT + (((size_t)b*66 + y + 1)*66 + xx + 1)*512 + row0;
        uint4* d4 = reinterpret_cast<uint4*>(dst);
        const uint4* s4 = reinterpret_cast<const uint4*>(&trans[t][0]);
        #pragma unroll
        for (int g = 0; g < 16; g++) d4[g] = s4[g];
    }
}

// ================= launch =================
extern "C" void kernel_launch(void* const* d_in, const int* in_sizes, int n_in,
                              void* d_out, int out_size)
{
    const float* x  = (const float*)d_in[0];
    const float* up = (const float*)d_in[1];
    const float* wq = (const float*)d_in[2];
    const float* sq = (const float*)d_in[3];
    const float* bq = (const float*)d_in[4];
    const float* wk = (const float*)d_in[5];
    const float* sk = (const float*)d_in[6];
    const float* bk = (const float*)d_in[7];
    const float* wv = (const float*)d_in[8];
    const float* sv = (const float*)d_in[9];
    const float* bv = (const float*)d_in[10];
    const float* wo = (const float*)d_in[11];
    const float* so = (const float*)d_in[12];
    const float* bo = (const float*)d_in[13];
    const float* ws = (const float*)d_in[14];
    const float* ss = (const float*)d_in[15];
    const float* bs = (const float*)d_in[16];
    float* out = (float*)d_out;

    prepxt<<<9160, 256>>>(x, wq, wk, wv, ws);
    qkv_mma<<<dim3(32, 5, 8), 128>>>(sq, bq, sk, bk, sv, bv);
    sim_mma<<<dim3(4, 4, 8), 128>>>();
    sim_reduce<<<(BB * CIN * CKD + 255) / 256, 256>>>();
    wos_kernel<<<dim3(8, 8), 256>>>(wo);
    fuse_mma<<<dim3(32, 4, 8), 128>>>(x, up, so, bo);
    conv_mma<<<dim3(32, 1, 8), 256>>>(ss, bs, out);
}

// round 17
// speedup vs baseline: 1.0128x; 1.0128x over previous
#include <cuda_runtime.h>
#include <cuda_fp16.h>
#include <math.h>

#define BB 8
#define CIN 512
#define NPIX 4096
#define CKD 64
#define COUT 128
#define KCONV 4608

typedef __half h16;

// ---------------- device scratch ----------------
__device__ __align__(16) h16 g_XT[(size_t)BB*NPIX*512];        // [b][n][c512] fp16
__device__ __align__(16) h16 g_fuseT[(size_t)BB*66*66*512];    // [b][y][x][c512] fp16
__device__ __align__(16) h16 g_Wqk[128*512];                   // hi only
__device__ __align__(16) h16 g_Wv[512*512];                    // hi only
__device__ __align__(16) h16 g_Wc[128*KCONV];                  // hi only, k'=(r9*512+ic)
__device__ __align__(16) h16 g_Vh[(size_t)BB*CIN*2*NPIX];      // [b][c][hi|lo][n]
__device__ __align__(16) h16 g_Kh[(size_t)BB*CKD*2*NPIX];      // [b][k][hi|lo][n]
__device__ __align__(16) h16 g_QT[(size_t)BB*NPIX*64];         // [b][n][hi64]
__device__ __align__(16) h16 g_WosH[BB*CIN*128];               // [b][o][hi64|lo64]
__device__ float g_simP[BB*4*CIN*CKD];
__device__ float g_simT[BB*CIN*CKD];

// ---------------- helpers ----------------
__device__ __forceinline__ unsigned pk2h(float a, float b) {
    __half2 h = __floats2half2_rn(a, b);
    return *reinterpret_cast<unsigned*>(&h);
}
__device__ __forceinline__ float hhi_f(float x) { return __half2float(__float2half_rn(x)); }
__device__ __forceinline__ void pack8h(const float* f, unsigned* hi) {
    #pragma unroll
    for (int i = 0; i < 4; i++) hi[i] = pk2h(f[2*i], f[2*i+1]);
}
__device__ __forceinline__ unsigned su32(const void* p) {
    return (unsigned)__cvta_generic_to_shared(p);
}
__device__ __forceinline__ void cpa16(void* sdst, const void* gsrc) {
    asm volatile("cp.async.cg.shared.global [%0], [%1], 16;" :: "r"(su32(sdst)), "l"(gsrc));
}
__device__ __forceinline__ void cp_commit() { asm volatile("cp.async.commit_group;" ::: "memory"); }
__device__ __forceinline__ void cp_wait2()  { asm volatile("cp.async.wait_group 2;" ::: "memory"); }
__device__ __forceinline__ void cp_wait1()  { asm volatile("cp.async.wait_group 1;" ::: "memory"); }
__device__ __forceinline__ void cp_wait0()  { asm volatile("cp.async.wait_group 0;" ::: "memory"); }
__device__ __forceinline__ void mma16816h(float* d, const unsigned* a, const unsigned* b) {
    asm("mma.sync.aligned.m16n8k16.row.col.f32.f16.f16.f32 "
        "{%0,%1,%2,%3},{%4,%5,%6,%7},{%8,%9},{%0,%1,%2,%3};"
        : "+f"(d[0]), "+f"(d[1]), "+f"(d[2]), "+f"(d[3])
        : "r"(a[0]), "r"(a[1]), "r"(a[2]), "r"(a[3]), "r"(b[0]), "r"(b[1]));
}
__device__ __forceinline__ void ldm4(unsigned* r, const h16* p) {
    asm volatile("ldmatrix.sync.aligned.m8n8.x4.shared.b16 {%0,%1,%2,%3}, [%4];"
        : "=r"(r[0]), "=r"(r[1]), "=r"(r[2]), "=r"(r[3]) : "r"(su32(p)));
}

// ---------------- prepxt: xt transpose + weight splits + conv permute + border zero ----
__global__ __launch_bounds__(256) void prepxt(
    const float* __restrict__ x,
    const float* __restrict__ wq, const float* __restrict__ wk,
    const float* __restrict__ wv, const float* __restrict__ ws)
{
    __shared__ float tile[32][65];
    const int bid = blockIdx.x;
    const int t = threadIdx.x;
    if (bid < 8192) {
        int b  = bid >> 10;
        int r2 = bid & 1023;
        int c0 = (r2 >> 6) * 32;
        int n0 = (r2 & 63) * 64;
        {
            int r = t >> 3, nq = (t & 7) * 8;
            const float* src = x + ((size_t)b * CIN + c0 + r) * NPIX + n0 + nq;
            float4 a = *reinterpret_cast<const float4*>(src);
            float4 c = *reinterpret_cast<const float4*>(src + 4);
            tile[r][nq+0]=a.x; tile[r][nq+1]=a.y; tile[r][nq+2]=a.z; tile[r][nq+3]=a.w;
            tile[r][nq+4]=c.x; tile[r][nq+5]=c.y; tile[r][nq+6]=c.z; tile[r][nq+7]=c.w;
        }
        __syncthreads();
        {
            int xc = t & 63, grp = t >> 6;
            float f[8];
            #pragma unroll
            for (int i = 0; i < 8; i++) f[i] = tile[grp*8 + i][xc];
            unsigned hh[4];
            pack8h(f, hh);
            h16* d = g_XT + ((size_t)b * NPIX + n0 + xc) * 512 + c0 + grp*8;
            *reinterpret_cast<uint4*>(d) = make_uint4(hh[0], hh[1], hh[2], hh[3]);
        }
        return;
    }
    const int pb = bid - 8192;
    if (pb < 160) {
        const float* src;
        h16* dst;
        int idx;
        if (pb < 16)      { src = wq; dst = g_Wqk;            idx = pb*256 + t; }
        else if (pb < 32) { src = wk; dst = g_Wqk + 64*512;   idx = (pb-16)*256 + t; }
        else              { src = wv; dst = g_Wv;             idx = (pb-32)*256 + t; }
        int m = idx >> 6, kg = idx & 63;
        float f[8];
        *reinterpret_cast<float4*>(f)     = *reinterpret_cast<const float4*>(src + (size_t)m*512 + kg*8);
        *reinterpret_cast<float4*>(f + 4) = *reinterpret_cast<const float4*>(src + (size_t)m*512 + kg*8 + 4);
        unsigned hi[4];
        pack8h(f, hi);
        *reinterpret_cast<uint4*>(dst + (size_t)m * 512 + kg*8) = make_uint4(hi[0], hi[1], hi[2], hi[3]);
    } else if (pb < 448) {
        int idx = (pb - 160) * 256 + t;
        if (idx >= 128 * 576) return;
        int oc = idx / 576, kg = idx - oc * 576;
        int kp0 = kg * 8;
        int r9 = kp0 >> 9, ic = kp0 & 511;
        float f[8];
        #pragma unroll
        for (int j = 0; j < 8; j++)
            f[j] = ws[(size_t)oc * KCONV + (ic + j) * 9 + r9];
        unsigned hi[4];
        pack8h(f, hi);
        *reinterpret_cast<uint4*>(g_Wc + (size_t)oc * KCONV + kp0) = make_uint4(hi[0], hi[1], hi[2], hi[3]);
    } else {
        int idx = (pb - 448) * 256 + t;
        if (idx >= BB * 260 * 64) return;
        int c16 = idx & 63;
        int r = idx >> 6;
        int b = r / 260, p = r - b * 260;
        int y, x2;
        if (p < 66)       { y = 0;  x2 = p; }
        else if (p < 132) { y = 65; x2 = p - 66; }
        else if (p < 196) { y = p - 132 + 1; x2 = 0; }
        else              { y = p - 196 + 1; x2 = 65; }
        uint4* d = reinterpret_cast<uint4*>(g_fuseT + (((size_t)b*66 + y)*66 + x2)*512);
        d[c16] = make_uint4(0, 0, 0, 0);
    }
}

// ---------------- qk/conv GEMMs: 256 threads, 64x32 warp tiles, 3-stage ----------
template<int MODE>   // 0=qk, 2=conv
__global__ __launch_bounds__(256) void mma_gemm(
    const float* __restrict__ s0, const float* __restrict__ b0v,
    const float* __restrict__ s1, const float* __restrict__ b1v,
    float* __restrict__ outp)
{
    constexpr int KD = (MODE == 2) ? KCONV : 512;
    constexpr int NSTEP = KD / 16;
    __shared__ __align__(16) h16 sm[3][2][128][24];   // 36KB, 3 stages
    const int bidx = blockIdx.z;
    const int n0 = blockIdx.x * 128;
    const int row0 = blockIdx.y * 128;
    const int t = threadIdx.x;
    const int lane = t & 31, w = t >> 5, wm = w >> 2, wn = w & 3;

    float acc[4][4][4];
    #pragma unroll
    for (int i = 0; i < 4; i++)
        #pragma unroll
        for (int j = 0; j < 4; j++)
            #pragma unroll
            for (int c = 0; c < 4; c++) acc[i][j][c] = 0.f;

    const h16* W = (MODE == 0) ? g_Wqk : g_Wc;
    const int lt = t >> 7, lr = t & 127;
    const h16* aSrc = W + (size_t)(row0 + lr) * KD;
    const h16* bSrcX = g_XT + ((size_t)bidx * NPIX + n0 + lr) * 512;
    int yi = 0, xi = 0;
    if (MODE == 2) { int p = n0 + lr; yi = p >> 6; xi = p & 63; }

    auto load = [&](int st, int kc) {
        if (lt == 0) {
            cpa16(&sm[st][0][lr][0], aSrc + kc);
            cpa16(&sm[st][0][lr][8], aSrc + kc + 8);
        } else {
            const h16* bp;
            if (MODE == 2) {
                int r9 = kc >> 9, kin = kc & 511;
                int dy = r9 / 3, dx = r9 - dy*3;
                bp = g_fuseT + (((size_t)bidx*66 + yi + dy)*66 + xi + dx)*512 + kin;
            } else {
                bp = bSrcX + kc;
            }
            cpa16(&sm[st][1][lr][0], bp);
            cpa16(&sm[st][1][lr][8], bp + 8);
        }
        cp_commit();
    };

    const int ar  = wm*64 + (lane & 15);
    const int acl = (lane >> 4) * 8;
    const int br  = wn*32 + ((lane >> 4) << 3) + (lane & 7);
    const int bcl = ((lane >> 3) & 1) * 8;

    load(0, 0);
    load(1, 16);
    int stq = 2;
    #pragma unroll 1
    for (int kt = 0; kt < NSTEP; kt++) {
        int cur = kt % 3;
        if (kt + 2 < NSTEP) {
            load(stq, (kt+2)*16);
            stq = (stq + 1) % 3;
            cp_wait2();
        } else if (kt + 1 < NSTEP) {
            cp_wait1();
        } else {
            cp_wait0();
        }
        __syncthreads();

        unsigned ah[4][4], bfr[4][2];
        #pragma unroll
        for (int mt = 0; mt < 4; mt++) ldm4(ah[mt], &sm[cur][0][ar + mt*16][acl]);
        #pragma unroll
        for (int g = 0; g < 2; g++) ldm4(&bfr[2*g][0], &sm[cur][1][br + g*16][bcl]);
        #pragma unroll
        for (int mt = 0; mt < 4; mt++)
            #pragma unroll
            for (int nt = 0; nt < 4; nt++)
                mma16816h(acc[mt][nt], ah[mt], bfr[nt]);
        __syncthreads();
    }

    const int qr = lane >> 2, qc = (lane & 3) * 2;

    if (MODE == 0) {
        #pragma unroll
        for (int mt = 0; mt < 4; mt++)
            #pragma unroll
            for (int h = 0; h < 2; h++) {
                int ri = (mt*16 + qr + 8*h) & 63;
                float sc = wm ? s1[ri] : s0[ri];
                float bi = wm ? b1v[ri] : b0v[ri];
                #pragma unroll
                for (int nt = 0; nt < 4; nt++) {
                    acc[mt][nt][2*h]   = fmaf(acc[mt][nt][2*h],   sc, bi);
                    acc[mt][nt][2*h+1] = fmaf(acc[mt][nt][2*h+1], sc, bi);
                }
            }
        float inv[4][2];
        #pragma unroll
        for (int nt = 0; nt < 4; nt++)
            #pragma unroll
            for (int j = 0; j < 2; j++) {
                float ss = 0.f;
                #pragma unroll
                for (int mt = 0; mt < 4; mt++)
                    ss += acc[mt][nt][j]*acc[mt][nt][j] + acc[mt][nt][2+j]*acc[mt][nt][2+j];
                ss += __shfl_xor_sync(0xffffffffu, ss, 4);
                ss += __shfl_xor_sync(0xffffffffu, ss, 8);
                ss += __shfl_xor_sync(0xffffffffu, ss, 16);
                inv[nt][j] = 1.f / fmaxf(sqrtf(ss), 1e-12f);
            }
        if (wm == 0) {
            h16* qd = g_QT + (size_t)bidx * NPIX * 64;
            #pragma unroll
            for (int mt = 0; mt < 4; mt++)
                #pragma unroll
                for (int h = 0; h < 2; h++) {
                    int ch = (mt*16 + qr + 8*h) & 63;
                    #pragma unroll
                    for (int nt = 0; nt < 4; nt++) {
                        int col = n0 + wn*32 + nt*8 + qc;
                        qd[(size_t)col*64 + ch]     = __float2half_rn(acc[mt][nt][2*h]   * inv[nt][0]);
                        qd[(size_t)(col+1)*64 + ch] = __float2half_rn(acc[mt][nt][2*h+1] * inv[nt][1]);
                    }
                }
        } else {
            #pragma unroll
            for (int mt = 0; mt < 4; mt++)
                #pragma unroll
                for (int h = 0; h < 2; h++) {
                    int ch = (mt*16 + qr + 8*h) & 63;
                    h16* kd = g_Kh + ((size_t)bidx * CKD + ch) * 2 * NPIX;
                    #pragma unroll
                    for (int nt = 0; nt < 4; nt++) {
                        int col = n0 + wn*32 + nt*8 + qc;
                        float v0 = acc[mt][nt][2*h]   * inv[nt][0];
                        float v1 = acc[mt][nt][2*h+1] * inv[nt][1];
                        *reinterpret_cast<unsigned*>(&kd[col]) = pk2h(v0, v1);
                        *reinterpret_cast<unsigned*>(&kd[NPIX + col]) =
                            pk2h(v0 - hhi_f(v0), v1 - hhi_f(v1));
                    }
                }
        }
    } else {
        #pragma unroll
        for (int mt = 0; mt < 4; mt++)
            #pragma unroll
            for (int h = 0; h < 2; h++) {
                int row = row0 + wm*64 + mt*16 + qr + 8*h;
                float sc = s0[row], bi = b0v[row];
                #pragma unroll
                for (int nt = 0; nt < 4; nt++) {
                    int col = n0 + wn*32 + nt*8 + qc;
                    float2 o;
                    o.x = fmaxf(fmaf(acc[mt][nt][2*h],   sc, bi), 0.f);
                    o.y = fmaxf(fmaf(acc[mt][nt][2*h+1], sc, bi), 0.f);
                    *reinterpret_cast<float2*>(
                        &outp[((size_t)bidx * COUT + row) * NPIX + col]) = o;
                }
            }
    }
}

// ---------------- V GEMM: 128 threads, 64x64 warp tiles, 3-stage ----------------
__global__ __launch_bounds__(128) void v_mma(
    const float* __restrict__ s0, const float* __restrict__ b0v)
{
    constexpr int NSTEP = 512 / 16;
    __shared__ __align__(16) h16 sm[3][2][128][24];   // 36KB, 3 stages
    const int bidx = blockIdx.z;
    const int n0 = blockIdx.x * 128;
    const int row0 = blockIdx.y * 128;
    const int t = threadIdx.x;
    const int lane = t & 31, w = t >> 5, wm = w >> 1, wn = w & 1;

    float acc[4][8][4];
    #pragma unroll
    for (int i = 0; i < 4; i++)
        #pragma unroll
        for (int j = 0; j < 8; j++)
            #pragma unroll
            for (int c = 0; c < 4; c++) acc[i][j][c] = 0.f;

    const h16* aSrc = g_Wv + (size_t)(row0 + t) * 512;
    const h16* bSrc = g_XT + ((size_t)bidx * NPIX + n0 + t) * 512;

    auto load = [&](int st, int kc) {
        cpa16(&sm[st][0][t][0], aSrc + kc);
        cpa16(&sm[st][0][t][8], aSrc + kc + 8);
        cpa16(&sm[st][1][t][0], bSrc + kc);
        cpa16(&sm[st][1][t][8], bSrc + kc + 8);
        cp_commit();
    };

    const int ar  = wm*64 + (lane & 15);
    const int acl = (lane >> 4) * 8;
    const int br  = wn*64 + ((lane >> 4) << 3) + (lane & 7);
    const int bcl = ((lane >> 3) & 1) * 8;

    load(0, 0);
    load(1, 16);
    int stq = 2;
    #pragma unroll 1
    for (int kt = 0; kt < NSTEP; kt++) {
        int cur = kt % 3;
        if (kt + 2 < NSTEP) {
            load(stq, (kt+2)*16);
            stq = (stq + 1) % 3;
            cp_wait2();
        } else if (kt + 1 < NSTEP) {
            cp_wait1();
        } else {
            cp_wait0();
        }
        __syncthreads();

        unsigned ah[4][4], bfr[8][2];
        #pragma unroll
        for (int mt = 0; mt < 4; mt++) ldm4(ah[mt], &sm[cur][0][ar + mt*16][acl]);
        #pragma unroll
        for (int g = 0; g < 4; g++) ldm4(&bfr[2*g][0], &sm[cur][1][br + g*16][bcl]);
        #pragma unroll
        for (int mt = 0; mt < 4; mt++)
            #pragma unroll
            for (int nt = 0; nt < 8; nt++)
                mma16816h(acc[mt][nt], ah[mt], bfr[nt]);
        __syncthreads();
    }

    const int qr = lane >> 2, qc = (lane & 3) * 2;
    #pragma unroll
    for (int mt = 0; mt < 4; mt++)
        #pragma unroll
        for (int h = 0; h < 2; h++) {
            int row = row0 + wm*64 + mt*16 + qr + 8*h;
            float sc = s0[row], bi = b0v[row];
            h16* vd = g_Vh + ((size_t)bidx * CIN + row) * 2 * NPIX;
            #pragma unroll
            for (int nt = 0; nt < 8; nt++) {
                int col = n0 + wn*64 + nt*8 + qc;
                float v0 = fmaxf(fmaf(acc[mt][nt][2*h],   sc, bi), 0.f);
                float v1 = fmaxf(fmaf(acc[mt][nt][2*h+1], sc, bi), 0.f);
                *reinterpret_cast<unsigned*>(&vd[col]) = pk2h(v0, v1);
                *reinterpret_cast<unsigned*>(&vd[NPIX + col]) =
                    pk2h(v0 - hhi_f(v0), v1 - hhi_f(v1));
            }
        }
}

// ---------------- sim via mma: 3-pass on split V/K ----------------
__global__ __launch_bounds__(128) void sim_mma()
{
    __shared__ __align__(16) h16 sm[2][4][128][24];   // 48KB
    const int b = blockIdx.z, chunk = blockIdx.y, c0 = blockIdx.x * 128;
    const int t = threadIdx.x;
    const int lane = t & 31, w = t >> 5, wm = w >> 1, wn = w & 1;

    float acc[4][4][4];
    #pragma unroll
    for (int i = 0; i < 4; i++)
        #pragma unroll
        for (int j = 0; j < 4; j++)
            #pragma unroll
            for (int c = 0; c < 4; c++) acc[i][j][c] = 0.f;

    const h16* aSrc = g_Vh + ((size_t)b * CIN + c0 + t) * 2 * NPIX + chunk * 1024;
    const h16* bSrc = g_Kh + ((size_t)b * CKD + (t & 63)) * 2 * NPIX + chunk * 1024;

    auto load = [&](int st, int kc) {
        cpa16(&sm[st][0][t][0], aSrc + kc);
        cpa16(&sm[st][0][t][8], aSrc + kc + 8);
        cpa16(&sm[st][1][t][0], aSrc + NPIX + kc);
        cpa16(&sm[st][1][t][8], aSrc + NPIX + kc + 8);
        if (t < 64) {
            cpa16(&sm[st][2][t][0], bSrc + kc);
            cpa16(&sm[st][2][t][8], bSrc + kc + 8);
            cpa16(&sm[st][3][t][0], bSrc + NPIX + kc);
            cpa16(&sm[st][3][t][8], bSrc + NPIX + kc + 8);
        }
        cp_commit();
    };

    const int ar  = wm*64 + (lane & 15);
    const int acl = (lane >> 4) * 8;
    const int br  = wn*32 + ((lane >> 4) << 3) + (lane & 7);
    const int bcl = ((lane >> 3) & 1) * 8;

    load(0, 0);
    #pragma unroll 1
    for (int kt = 0; kt < 64; kt++) {
        int cur = kt & 1;
        if (kt + 1 < 64) { load(cur ^ 1, (kt+1)*16); cp_wait1(); }
        else              cp_wait0();
        __syncthreads();

        unsigned ah[4][4], al[4][4], bh[4][2], bl[4][2];
        #pragma unroll
        for (int mt = 0; mt < 4; mt++) ldm4(ah[mt], &sm[cur][0][ar + mt*16][acl]);
        #pragma unroll
        for (int mt = 0; mt < 4; mt++) ldm4(al[mt], &sm[cur][1][ar + mt*16][acl]);
        #pragma unroll
        for (int g = 0; g < 2; g++) ldm4(&bh[2*g][0], &sm[cur][2][br + g*16][bcl]);
        #pragma unroll
        for (int g = 0; g < 2; g++) ldm4(&bl[2*g][0], &sm[cur][3][br + g*16][bcl]);
        #pragma unroll
        for (int mt = 0; mt < 4; mt++)
            #pragma unroll
            for (int nt = 0; nt < 4; nt++)
                mma16816h(acc[mt][nt], ah[mt], bh[nt]);
        #pragma unroll
        for (int mt = 0; mt < 4; mt++)
            #pragma unroll
            for (int nt = 0; nt < 4; nt++)
                mma16816h(acc[mt][nt], al[mt], bh[nt]);
        #pragma unroll
        for (int mt = 0; mt < 4; mt++)
            #pragma unroll
            for (int nt = 0; nt < 4; nt++)
                mma16816h(acc[mt][nt], ah[mt], bl[nt]);
        __syncthreads();
    }

    const int qr = lane >> 2, qc = (lane & 3) * 2;
    float* pb = g_simP + (size_t)(b*4 + chunk) * CIN * CKD;
    #pragma unroll
    for (int mt = 0; mt < 4; mt++)
        #pragma unroll
        for (int h = 0; h < 2; h++) {
            int row = c0 + wm*64 + mt*16 + qr + 8*h;
            #pragma unroll
            for (int nt = 0; nt < 4; nt++) {
                int col = wn*32 + nt*8 + qc;
                float2 o = make_float2(acc[mt][nt][2*h], acc[mt][nt][2*h+1]);
                *reinterpret_cast<float2*>(&pb[(size_t)row * CKD + col]) = o;
            }
        }
}

__global__ __launch_bounds__(256) void sim_reduce()
{
    int idx = blockIdx.x * 256 + threadIdx.x;
    if (idx >= BB * CIN * CKD) return;
    int b = idx / (CIN * CKD);
    int rem = idx - b * CIN * CKD;
    float s = 0.f;
    #pragma unroll
    for (int p = 0; p < 4; p++)
        s += g_simP[(size_t)(b*4 + p) * CIN * CKD + rem];
    g_simT[idx] = s;
}

// ---------------- wos: Wo @ simT -> split fp16 [b][o][hi64|lo64] ----------------
__global__ __launch_bounds__(256) void wos_kernel(const float* __restrict__ wo)
{
    __shared__ __align__(16) float As[16][64];
    __shared__ __align__(16) float Bs[16][64];
    const int b = blockIdx.y;
    const int row0 = blockIdx.x * 64;
    const float* ST = g_simT + (size_t)b * CIN * CKD;
    const int t = threadIdx.x;
    const int tr = t >> 4, tc = t & 15;
    float acc[4][4];
    #pragma unroll
    for (int i = 0; i < 4; i++)
        #pragma unroll
        for (int j = 0; j < 4; j++) acc[i][j] = 0.f;

    for (int kb = 0; kb < CIN; kb += 16) {
        {
            int r  = t >> 2;
            int k4 = (t & 3) << 2;
            float4 va = *reinterpret_cast<const float4*>(wo + (size_t)(row0 + r) * CIN + kb + k4);
            As[k4+0][r] = va.x; As[k4+1][r] = va.y; As[k4+2][r] = va.z; As[k4+3][r] = va.w;
            int kk = t >> 4;
            int n4 = (t & 15) << 2;
            *reinterpret_cast<float4*>(&Bs[kk][n4]) =
                *reinterpret_cast<const float4*>(ST + (size_t)(kb + kk) * CKD + n4);
        }
        __syncthreads();
        #pragma unroll
        for (int kk = 0; kk < 16; kk++) {
            float4 a = *reinterpret_cast<float4*>(&As[kk][tr*4]);
            float4 bbv = *reinterpret_cast<float4*>(&Bs[kk][tc*4]);
            float av[4] = {a.x,a.y,a.z,a.w};
            float bv[4] = {bbv.x,bbv.y,bbv.z,bbv.w};
            #pragma unroll
            for (int i = 0; i < 4; i++)
                #pragma unroll
                for (int j = 0; j < 4; j++)
                    acc[i][j] = fmaf(av[i], bv[j], acc[i][j]);
        }
        __syncthreads();
    }
    #pragma unroll
    for (int i = 0; i < 4; i++) {
        int o = row0 + tr * 4 + i;
        float v0 = acc[i][0], v1 = acc[i][1], v2 = acc[i][2], v3 = acc[i][3];
        h16* d = g_WosH + ((size_t)b * CIN + o) * 128 + tc*4;
        *reinterpret_cast<uint2*>(d) =
            make_uint2(pk2h(v0, v1), pk2h(v2, v3));
        *reinterpret_cast<uint2*>(d + 64) =
            make_uint2(pk2h(v0 - hhi_f(v0), v1 - hhi_f(v1)),
                       pk2h(v2 - hhi_f(v2), v3 - hhi_f(v3)));
    }
}

// ---------------- fuse via mma: 2-pass (Wos hi+lo, Q hi) ----------------
__global__ __launch_bounds__(128) void fuse_mma(
    const float* __restrict__ x, const float* __restrict__ up,
    const float* __restrict__ so, const float* __restrict__ bo)
{
    __shared__ __align__(16) h16 sm[2][3][128][24];   // 36KB; reused as transpose buf
    const int b = blockIdx.z;
    const int n0 = blockIdx.x * 128;
    const int row0 = blockIdx.y * 128;
    const int t = threadIdx.x;
    const int lane = t & 31, w = t >> 5, wm = w >> 1, wn = w & 1;

    float acc[4][8][4];
    #pragma unroll
    for (int i = 0; i < 4; i++)
        #pragma unroll
        for (int j = 0; j < 8; j++)
            #pragma unroll
            for (int c = 0; c < 4; c++) acc[i][j][c] = 0.f;

    const h16* aSrc = g_WosH + ((size_t)b * CIN + row0 + t) * 128;
    const h16* bSrc = g_QT   + ((size_t)b * NPIX + n0 + t) * 64;

    auto load = [&](int st, int kc) {
        cpa16(&sm[st][0][t][0], aSrc + kc);
        cpa16(&sm[st][0][t][8], aSrc + kc + 8);
        cpa16(&sm[st][1][t][0], aSrc + 64 + kc);
        cpa16(&sm[st][1][t][8], aSrc + 64 + kc + 8);
        cpa16(&sm[st][2][t][0], bSrc + kc);
        cpa16(&sm[st][2][t][8], bSrc + kc + 8);
        cp_commit();
    };

    const int ar  = wm*64 + (lane & 15);
    const int acl = (lane >> 4) * 8;
    const int br  = wn*64 + ((lane >> 4) << 3) + (lane & 7);
    const int bcl = ((lane >> 3) & 1) * 8;

    load(0, 0);
    #pragma unroll 1
    for (int kt = 0; kt < 4; kt++) {
        int cur = kt & 1;
        if (kt + 1 < 4) { load(cur ^ 1, (kt+1)*16); cp_wait1(); }
        else             cp_wait0();
        __syncthreads();

        unsigned ah[4][4], al[4][4], bh[8][2];
        #pragma unroll
        for (int mt = 0; mt < 4; mt++) ldm4(ah[mt], &sm[cur][0][ar + mt*16][acl]);
        #pragma unroll
        for (int mt = 0; mt < 4; mt++) ldm4(al[mt], &sm[cur][1][ar + mt*16][acl]);
        #pragma unroll
        for (int g = 0; g < 4; g++) ldm4(&bh[2*g][0], &sm[cur][2][br + g*16][bcl]);
        #pragma unroll
        for (int mt = 0; mt < 4; mt++)
            #pragma unroll
            for (int nt = 0; nt < 8; nt++)
                mma16816h(acc[mt][nt], ah[mt], bh[nt]);        // hi*hi
        #pragma unroll
        for (int mt = 0; mt < 4; mt++)
            #pragma unroll
            for (int nt = 0; nt < 8; nt++)
                mma16816h(acc[mt][nt], al[mt], bh[nt]);        // lo*hi
        __syncthreads();
    }

    const int qr = lane >> 2, qc = (lane & 3) * 2;
    h16 (*trans)[136] = reinterpret_cast<h16 (*)[136]>(&sm[0][0][0][0]);
    #pragma unroll
    for (int mt = 0; mt < 4; mt++)
        #pragma unroll
        for (int h = 0; h < 2; h++) {
            int crl = wm*64 + mt*16 + qr + 8*h;
            int row = row0 + crl;
            float sc = so[row], bi = bo[row];
            #pragma unroll
            for (int nt = 0; nt < 8; nt++) {
                int cl = wn*64 + nt*8 + qc;
                size_t xoff = ((size_t)b * CIN + row) * NPIX + n0 + cl;
                float2 xv = *reinterpret_cast<const float2*>(x + xoff);
                float2 uv = *reinterpret_cast<const float2*>(up + xoff);
                float v0 = fmaxf(fmaf(acc[mt][nt][2*h],   sc, bi), 0.f) + xv.x + uv.x;
                float v1 = fmaxf(fmaf(acc[mt][nt][2*h+1], sc, bi), 0.f) + xv.y + uv.y;
                trans[cl][crl]     = __float2half_rn(v0);
                trans[cl + 1][crl] = __float2half_rn(v1);
            }
        }
    __syncthreads();
    {
        int p = n0 + t;
        int y = p >> 6, xx = p & 63;
        h16* dst = g_fuseT + (((size_t)b*66 + y + 1)*66 + xx + 1)*512 + row0;
        uint4* d4 = reinterpret_cast<uint4*>(dst);
        const uint4* s4 = reinterpret_cast<const uint4*>(&trans[t][0]);
        #pragma unroll
        for (int g = 0; g < 16; g++) d4[g] = s4[g];
    }
}

// ================= launch =================
extern "C" void kernel_launch(void* const* d_in, const int* in_sizes, int n_in,
                              void* d_out, int out_size)
{
    const float* x  = (const float*)d_in[0];
    const float* up = (const float*)d_in[1];
    const float* wq = (const float*)d_in[2];
    const float* sq = (const float*)d_in[3];
    const float* bq = (const float*)d_in[4];
    const float* wk = (const float*)d_in[5];
    const float* sk = (const float*)d_in[6];
    const float* bk = (const float*)d_in[7];
    const float* wv = (const float*)d_in[8];
    const float* sv = (const float*)d_in[9];
    const float* bv = (const float*)d_in[10];
    const float* wo = (const float*)d_in[11];
    const float* so = (const float*)d_in[12];
    const float* bo = (const float*)d_in[13];
    const float* ws = (const float*)d_in[14];
    const float* ss = (const float*)d_in[15];
    const float* bs = (const float*)d_in[16];
    float* out = (float*)d_out;

    prepxt<<<9160, 256>>>(x, wq, wk, wv, ws);
    mma_gemm<0><<<dim3(32, 1, 8), 256>>>(sq, bq, sk, bk, nullptr);
    v_mma<<<dim3(32, 4, 8), 128>>>(sv, bv);
    sim_mma<<<dim3(4, 4, 8), 128>>>();
    sim_reduce<<<(BB * CIN * CKD + 255) / 256, 256>>>();
    wos_kernel<<<dim3(8, 8), 256>>>(wo);
    fuse_mma<<<dim3(32, 4, 8), 128>>>(x, up, so, bo);
    mma_gemm<2><<<dim3(32, 1, 8), 256>>>(ss, bs, nullptr, nullptr, out);
}